// round 6
// baseline (speedup 1.0000x reference)
#include <cuda_runtime.h>
#include <cuda_fp16.h>
#include <cstdint>

// ---------------- problem constants ----------------
#define NROWS 8192
#define DIN   12544
#define HID   1024

// ---------------- GEMM2 tile config (fp16 A path, unchanged from R5) ----------------
#define BM 128
#define BN 128
#define BK 64
#define ROWB 144
#define STAGE_BYTES ((BM + BN) * ROWB)     // 36864
#define SMEM_BYTES (3 * STAGE_BYTES)       // 110592

// ---------------- GEMM1 tile config (fp32 A fused-convert, BK=32) ----------------
#define BK1 32
#define A1_PITCH 144                        // 32 fp32 = 128B + 16B pad
#define B1_PITCH 80                         // 32 f16  = 64B  + 16B pad
#define A1_STAGE (BM * A1_PITCH)            // 18432
#define B1_STAGE (BN * B1_PITCH)            // 10240
#define STAGE1_BYTES (A1_STAGE + B1_STAGE)  // 28672
#define SMEM1_BYTES (3 * STAGE1_BYTES)      // 86016 -> 2 CTAs/SM

// ---------------- device scratch ----------------
__device__ __align__(256) __half g_W1T[(size_t)HID * DIN];
__device__ __align__(256) __half g_W2T[(size_t)HID * HID];
__device__ __align__(256) __half g_H1 [(size_t)NROWS * HID];
__device__ __align__(256) float  g_H2 [(size_t)NROWS * HID];

// ---------------- PTX helpers ----------------
__device__ __forceinline__ uint32_t smem_u32(const void* p) {
    uint32_t a;
    asm("{ .reg .u64 t; cvta.to.shared.u64 t, %1; cvt.u32.u64 %0, t; }" : "=r"(a) : "l"(p));
    return a;
}

#define CP_ASYNC16(dst, src) \
    asm volatile("cp.async.cg.shared.global [%0], [%1], 16;" :: "r"(dst), "l"(src) : "memory")
#define CP_ASYNC8(dst, src) \
    asm volatile("cp.async.ca.shared.global [%0], [%1], 8;" :: "r"(dst), "l"(src) : "memory")
#define CP_ASYNC_COMMIT() asm volatile("cp.async.commit_group;" ::: "memory")
#define CP_ASYNC_WAIT1()  asm volatile("cp.async.wait_group 1;" ::: "memory")

__device__ __forceinline__ void ldm_x4(uint32_t& r0, uint32_t& r1, uint32_t& r2, uint32_t& r3,
                                       uint32_t addr) {
    asm volatile("ldmatrix.sync.aligned.m8n8.x4.shared.b16 {%0,%1,%2,%3}, [%4];"
                 : "=r"(r0), "=r"(r1), "=r"(r2), "=r"(r3) : "r"(addr));
}

__device__ __forceinline__ float2 lds64(uint32_t addr) {
    float2 v;
    asm volatile("ld.shared.v2.f32 {%0,%1}, [%2];" : "=f"(v.x), "=f"(v.y) : "r"(addr));
    return v;
}

__device__ __forceinline__ uint32_t packh2(float lo, float hi) {
    __half2 h = __floats2half2_rn(lo, hi);
    return *reinterpret_cast<uint32_t*>(&h);
}

__device__ __forceinline__ void mma16816(float* d, const uint32_t* a, const uint32_t* b) {
    asm volatile(
        "mma.sync.aligned.m16n8k16.row.col.f32.f16.f16.f32 "
        "{%0,%1,%2,%3}, {%4,%5,%6,%7}, {%8,%9}, {%0,%1,%2,%3};"
        : "+f"(d[0]), "+f"(d[1]), "+f"(d[2]), "+f"(d[3])
        : "r"(a[0]), "r"(a[1]), "r"(a[2]), "r"(a[3]), "r"(b[0]), "r"(b[1]));
}

// ---------------- weight transpose (f32 -> f16, [R,C] -> [C,R]) ----------------
__global__ void __launch_bounds__(256) transpose_f32_to_f16(const float* __restrict__ in,
                                                            __half* __restrict__ out,
                                                            int R, int C) {
    __shared__ float tile[32][33];
    int c0 = blockIdx.x * 32, r0 = blockIdx.y * 32;
    int x = threadIdx.x, y = threadIdx.y;  // block (32, 8)
    #pragma unroll
    for (int j = 0; j < 32; j += 8)
        tile[y + j][x] = in[(size_t)(r0 + y + j) * C + (c0 + x)];
    __syncthreads();
    #pragma unroll
    for (int j = 0; j < 32; j += 8)
        out[(size_t)(c0 + y + j) * R + (r0 + x)] = __float2half_rn(tile[x][y + j]);
}

// ---------------- GEMM1: A fp32 (converted in-kernel), B f16, BK=32 ----------------
// H1[M, N] = X[M, K] (fp32, K-major) @ W1T[N, K]^T (f16) + b1, out f16.
// A smem layout: row pitch 144B; within a 128B row the 16 fp32-pairs are placed at
// byte(p) = 16*(p>>3) + 32*((p>>2)&1) + 64*(p&1) + 8*((p>>1)&1)   (p = k>>1)
// which makes the per-fragment LDS.64s bank-conflict-free.
__global__ void __launch_bounds__(256, 2)
gemm1_kernel(const float* __restrict__ A, const __half* __restrict__ B,
             const float* __restrict__ bias, __half* __restrict__ Cout,
             int K, int nk) {
    extern __shared__ char smem[];
    const uint32_t sb = smem_u32(smem);
    const int tid  = threadIdx.x;
    const int wid  = tid >> 5, lane = tid & 31;
    const int wm   = wid & 1;
    const int wn   = wid >> 1;
    const int m0   = blockIdx.y * BM;
    const int n0   = blockIdx.x * BN;

    // A producer mapping: 8B pair chunks; thread -> (pair col, row)
    const int apr  = tid & 15;            // pair index 0..15
    const int arw  = tid >> 4;            // row 0..15, 8 passes of +16
    const uint32_t abyte = 16 * (apr >> 3) + 32 * ((apr >> 2) & 1)
                         + 64 * (apr & 1) + 8 * ((apr >> 1) & 1);
    const float* gA = A + (size_t)(m0 + arw) * K + 2 * apr;

    // B producer mapping: 16B chunks, 4 per 64B row
    const int bc = tid & 3, brw = tid >> 2;   // row 0..63, 2 passes
    const char* gB = reinterpret_cast<const char*>(B) + ((size_t)(n0 + brw) * K) * 2 + bc * 16;

    auto issue_stage = [&](int kc, int s) {
        const uint32_t abase = sb + s * STAGE1_BYTES;
        const uint32_t bbase = abase + A1_STAGE;
        const float* srcA = gA + (size_t)kc * BK1;
        #pragma unroll
        for (int h = 0; h < 8; h++)   // A: 128 rows, 16 rows per pass
            CP_ASYNC8(abase + (arw + 16 * h) * A1_PITCH + abyte,
                      srcA + (size_t)16 * h * K);
        const char* srcB = gB + (size_t)kc * (BK1 * 2);
        #pragma unroll
        for (int h = 0; h < 2; h++)   // B: 128 rows, 64 per pass
            CP_ASYNC16(bbase + (brw + 64 * h) * B1_PITCH + bc * 16,
                       srcB + (size_t)64 * h * K * 2);
    };

    // fragment lane offsets
    const int a_r = lane >> 2, a_q = lane & 3;
    const uint32_t a_qb = 64 * (a_q & 1) + 8 * ((a_q >> 1) & 1);
    const int b_row = (lane & 7) + ((lane >> 4) << 3), b_k8 = (lane >> 3) & 1;

    float acc[4][4][4];
    #pragma unroll
    for (int i = 0; i < 4; i++)
        #pragma unroll
        for (int j = 0; j < 4; j++)
            #pragma unroll
            for (int r = 0; r < 4; r++) acc[i][j][r] = 0.f;

    issue_stage(0, 0); CP_ASYNC_COMMIT();
    issue_stage(1, 1); CP_ASYNC_COMMIT();

    int s = 0, s2 = 2;
    for (int kc = 0; kc < nk; kc++) {
        CP_ASYNC_WAIT1();
        __syncthreads();

        if (kc + 2 < nk) issue_stage(kc + 2, s2);
        CP_ASYNC_COMMIT();

        const uint32_t abase = sb + s * STAGE1_BYTES;
        const uint32_t bbase = abase + A1_STAGE;

        #pragma unroll
        for (int kk = 0; kk < 2; kk++) {   // two k16 steps per BK1=32
            uint32_t af[4][4], bf[4][2];
            #pragma unroll
            for (int mi = 0; mi < 4; mi++) {
                uint32_t rb = abase + (wm * 64 + mi * 16 + a_r) * A1_PITCH + kk * 16 + a_qb;
                float2 v0 = lds64(rb);                    // (row,   k0..7 pair)
                float2 v1 = lds64(rb + 8 * A1_PITCH);     // (row+8, k0..7)
                float2 v2 = lds64(rb + 32);               // (row,   k8..15)
                float2 v3 = lds64(rb + 32 + 8 * A1_PITCH);
                af[mi][0] = packh2(v0.x, v0.y);
                af[mi][1] = packh2(v1.x, v1.y);
                af[mi][2] = packh2(v2.x, v2.y);
                af[mi][3] = packh2(v3.x, v3.y);
            }
            #pragma unroll
            for (int nb = 0; nb < 2; nb++) {
                uint32_t addr = bbase + (wn * 32 + nb * 16 + b_row) * B1_PITCH
                              + (kk * 2 + b_k8) * 16;
                uint32_t r0, r1, r2, r3;
                ldm_x4(r0, r1, r2, r3, addr);
                bf[nb * 2][0] = r0;     bf[nb * 2][1] = r1;
                bf[nb * 2 + 1][0] = r2; bf[nb * 2 + 1][1] = r3;
            }
            #pragma unroll
            for (int mi = 0; mi < 4; mi++)
                #pragma unroll
                for (int nj = 0; nj < 4; nj++)
                    mma16816(acc[mi][nj], af[mi], bf[nj]);
        }
        s = (s == 2) ? 0 : s + 1;
        s2 = (s2 == 2) ? 0 : s2 + 1;
    }

    // epilogue: +bias, f16 out
    const int tq = lane >> 2, tr = lane & 3;
    #pragma unroll
    for (int nj = 0; nj < 4; nj++) {
        const int col = n0 + wn * 32 + nj * 8 + tr * 2;
        const float bx = bias[col], by = bias[col + 1];
        #pragma unroll
        for (int mi = 0; mi < 4; mi++) {
            const int row = m0 + wm * 64 + mi * 16 + tq;
            __half2 h0 = __floats2half2_rn(acc[mi][nj][0] + bx, acc[mi][nj][1] + by);
            __half2 h1 = __floats2half2_rn(acc[mi][nj][2] + bx, acc[mi][nj][3] + by);
            *reinterpret_cast<__half2*>(Cout + (size_t)row * HID + col) = h0;
            *reinterpret_cast<__half2*>(Cout + (size_t)(row + 8) * HID + col) = h1;
        }
    }
}

// ---------------- GEMM2: f16 A/B, BK=64 (R5 path), relu(+bias), f32 out ----------------
__global__ void __launch_bounds__(256, 2)
gemm2_kernel(const __half* __restrict__ A, const __half* __restrict__ B,
             const float* __restrict__ bias, float* __restrict__ Cout,
             int K, int nk) {
    extern __shared__ char smem[];
    const uint32_t sb = smem_u32(smem);
    const int tid  = threadIdx.x;
    const int wid  = tid >> 5, lane = tid & 31;
    const int wm   = wid & 1;
    const int wn   = wid >> 1;
    const int m0   = blockIdx.y * BM;
    const int n0   = blockIdx.x * BN;

    const int cr = tid >> 3;
    const int cc = (tid & 7) * 16;

    const char* gA = reinterpret_cast<const char*>(A) + ((size_t)(m0 + cr) * K) * 2 + cc;
    const char* gB = reinterpret_cast<const char*>(B) + ((size_t)(n0 + cr) * K) * 2 + cc;
    const size_t rstride = (size_t)32 * K * 2;

    auto issue_stage = [&](int kc, int s) {
        const uint32_t abase = sb + s * STAGE_BYTES;
        const uint32_t bbase = abase + BM * ROWB;
        const size_t koff = (size_t)kc * (BK * 2);
        #pragma unroll
        for (int h = 0; h < 4; h++)
            CP_ASYNC16(abase + (cr + h * 32) * ROWB + cc, gA + koff + h * rstride);
        #pragma unroll
        for (int h = 0; h < 4; h++)
            CP_ASYNC16(bbase + (cr + h * 32) * ROWB + cc, gB + koff + h * rstride);
    };

    const int a_row = lane & 15, a_k8 = lane >> 4;
    const int b_row = (lane & 7) + ((lane >> 4) << 3), b_k8 = (lane >> 3) & 1;

    float acc[4][4][4];
    #pragma unroll
    for (int i = 0; i < 4; i++)
        #pragma unroll
        for (int j = 0; j < 4; j++)
            #pragma unroll
            for (int r = 0; r < 4; r++) acc[i][j][r] = 0.f;

    issue_stage(0, 0); CP_ASYNC_COMMIT();
    if (nk > 1) issue_stage(1, 1); CP_ASYNC_COMMIT();

    int s = 0, s2 = 2;
    for (int kc = 0; kc < nk; kc++) {
        CP_ASYNC_WAIT1();
        __syncthreads();

        if (kc + 2 < nk) issue_stage(kc + 2, s2);
        CP_ASYNC_COMMIT();

        const uint32_t abase = sb + s * STAGE_BYTES;
        const uint32_t bbase = abase + BM * ROWB;

        #pragma unroll
        for (int kk = 0; kk < 4; kk++) {
            uint32_t af[4][4], bf[4][2];
            #pragma unroll
            for (int mi = 0; mi < 4; mi++) {
                uint32_t addr = abase + (wm * 64 + mi * 16 + a_row) * ROWB + (kk * 2 + a_k8) * 16;
                ldm_x4(af[mi][0], af[mi][1], af[mi][2], af[mi][3], addr);
            }
            #pragma unroll
            for (int nb = 0; nb < 2; nb++) {
                uint32_t addr = bbase + (wn * 32 + nb * 16 + b_row) * ROWB + (kk * 2 + b_k8) * 16;
                uint32_t r0, r1, r2, r3;
                ldm_x4(r0, r1, r2, r3, addr);
                bf[nb * 2][0] = r0;     bf[nb * 2][1] = r1;
                bf[nb * 2 + 1][0] = r2; bf[nb * 2 + 1][1] = r3;
            }
            #pragma unroll
            for (int mi = 0; mi < 4; mi++)
                #pragma unroll
                for (int nj = 0; nj < 4; nj++)
                    mma16816(acc[mi][nj], af[mi], bf[nj]);
        }
        s = (s == 2) ? 0 : s + 1;
        s2 = (s2 == 2) ? 0 : s2 + 1;
    }

    const int tq = lane >> 2, tr = lane & 3;
    #pragma unroll
    for (int nj = 0; nj < 4; nj++) {
        const int col = n0 + wn * 32 + nj * 8 + tr * 2;
        const float bx = bias[col], by = bias[col + 1];
        #pragma unroll
        for (int mi = 0; mi < 4; mi++) {
            const int row = m0 + wm * 64 + mi * 16 + tq;
            float2 f0 = make_float2(fmaxf(acc[mi][nj][0] + bx, 0.f), fmaxf(acc[mi][nj][1] + by, 0.f));
            float2 f1 = make_float2(fmaxf(acc[mi][nj][2] + bx, 0.f), fmaxf(acc[mi][nj][3] + by, 0.f));
            *reinterpret_cast<float2*>(Cout + (size_t)row * HID + col) = f0;
            *reinterpret_cast<float2*>(Cout + (size_t)(row + 8) * HID + col) = f1;
        }
    }
}

// ---------------- heads: logits softmax + box regression ----------------
__global__ void __launch_bounds__(128) heads_kernel(const float* __restrict__ H,
                                                    const float* __restrict__ Wc, const float* __restrict__ bc,
                                                    const float* __restrict__ Wr, const float* __restrict__ br,
                                                    float* __restrict__ out) {
    const int row = blockIdx.x;
    const int tid = threadIdx.x, lane = tid & 31, w = tid >> 5;
    __shared__ float part[4 * 16];
    __shared__ float res[16];

    float acc[16];
    #pragma unroll
    for (int o = 0; o < 16; o++) acc[o] = 0.f;

    const float* h = H + (size_t)row * HID;
    const float4* Wc4 = reinterpret_cast<const float4*>(Wc);
    const float4* Wr4 = reinterpret_cast<const float4*>(Wr);
    for (int k = tid; k < HID; k += 128) {
        float hv = h[k];
        float4 c = Wc4[k];
        acc[0] += hv * c.x; acc[1] += hv * c.y; acc[2] += hv * c.z; acc[3] += hv * c.w;
        float4 r0 = Wr4[k * 3], r1 = Wr4[k * 3 + 1], r2 = Wr4[k * 3 + 2];
        acc[4]  += hv * r0.x; acc[5]  += hv * r0.y; acc[6]  += hv * r0.z; acc[7]  += hv * r0.w;
        acc[8]  += hv * r1.x; acc[9]  += hv * r1.y; acc[10] += hv * r1.z; acc[11] += hv * r1.w;
        acc[12] += hv * r2.x; acc[13] += hv * r2.y; acc[14] += hv * r2.z; acc[15] += hv * r2.w;
    }
    #pragma unroll
    for (int o = 0; o < 16; o++) {
        float v = acc[o];
        v += __shfl_xor_sync(0xffffffffu, v, 16);
        v += __shfl_xor_sync(0xffffffffu, v, 8);
        v += __shfl_xor_sync(0xffffffffu, v, 4);
        v += __shfl_xor_sync(0xffffffffu, v, 2);
        v += __shfl_xor_sync(0xffffffffu, v, 1);
        if (lane == 0) part[w * 16 + o] = v;
    }
    __syncthreads();
    if (tid < 16) {
        float v = part[tid] + part[16 + tid] + part[32 + tid] + part[48 + tid];
        v += (tid < 4) ? bc[tid] : br[tid - 4];
        res[tid] = v;
    }
    __syncthreads();
    if (tid == 0) {
        float m = fmaxf(fmaxf(res[0], res[1]), fmaxf(res[2], res[3]));
        float e0 = expf(res[0] - m), e1 = expf(res[1] - m), e2 = expf(res[2] - m), e3 = expf(res[3] - m);
        float inv = 1.f / (e0 + e1 + e2 + e3);
        out[(size_t)row * 4 + 0] = e0 * inv;
        out[(size_t)row * 4 + 1] = e1 * inv;
        out[(size_t)row * 4 + 2] = e2 * inv;
        out[(size_t)row * 4 + 3] = e3 * inv;
    }
    if (tid >= 4 && tid < 16)
        out[(size_t)NROWS * 4 + (size_t)row * 12 + (tid - 4)] = res[tid];
}

// ---------------- launch ----------------
extern "C" void kernel_launch(void* const* d_in, const int* in_sizes, int n_in,
                              void* d_out, int out_size) {
    (void)in_sizes; (void)n_in; (void)out_size;
    const float* X  = (const float*)d_in[0];
    const float* W1 = (const float*)d_in[1];
    const float* b1 = (const float*)d_in[2];
    const float* W2 = (const float*)d_in[3];
    const float* b2 = (const float*)d_in[4];
    const float* Wc = (const float*)d_in[5];
    const float* bc = (const float*)d_in[6];
    const float* Wr = (const float*)d_in[7];
    const float* br = (const float*)d_in[8];
    float* out = (float*)d_out;

    void *pW1T, *pW2T, *pH1, *pH2;
    cudaGetSymbolAddress(&pW1T, g_W1T);
    cudaGetSymbolAddress(&pW2T, g_W2T);
    cudaGetSymbolAddress(&pH1,  g_H1);
    cudaGetSymbolAddress(&pH2,  g_H2);

    cudaFuncSetAttribute(gemm1_kernel, cudaFuncAttributeMaxDynamicSharedMemorySize, SMEM1_BYTES);
    cudaFuncSetAttribute(gemm2_kernel, cudaFuncAttributeMaxDynamicSharedMemorySize, SMEM_BYTES);

    // 1) W1 [DIN, HID] -> W1T [HID, DIN] f16 ; W2 -> W2T f16
    transpose_f32_to_f16<<<dim3(HID / 32, DIN / 32), dim3(32, 8)>>>(W1, (__half*)pW1T, DIN, HID);
    transpose_f32_to_f16<<<dim3(HID / 32, HID / 32), dim3(32, 8)>>>(W2, (__half*)pW2T, HID, HID);
    // 2) H1 = X @ W1 + b1  (fp32 A converted in-kernel, f16 out)
    gemm1_kernel<<<dim3(HID / BN, NROWS / BM), 256, SMEM1_BYTES>>>(
        X, (const __half*)pW1T, b1, (__half*)pH1, DIN, DIN / BK1);
    // 3) H2 = relu(H1 @ W2 + b2)  (f32 out)
    gemm2_kernel<<<dim3(HID / BN, NROWS / BM), 256, SMEM_BYTES>>>(
        (const __half*)pH1, (const __half*)pW2T, b2, (float*)pH2, HID, HID / BK);
    // 4) heads
    heads_kernel<<<NROWS, 128>>>((const float*)pH2, Wc, bc, Wr, br, out);
}

// round 7
// speedup vs baseline: 1.0022x; 1.0022x over previous
#include <cuda_runtime.h>
#include <cuda_fp16.h>
#include <cstdint>

// ---------------- problem constants ----------------
#define NROWS 8192
#define DIN   12544
#define HID   1024

// ---------------- shared tile config ----------------
#define BM 128
#define BN 128
#define BK 64
#define ROWB 144                           // 128B data + 16B pad
#define STAGE_BYTES ((BM + BN) * ROWB)     // 36864

// GEMM1 (fused convert): 2 stages, 384 threads (8 compute + 4 producer warps)
#define SMEM1_BYTES (2 * STAGE_BYTES)      // 73728
// GEMM2: 3 stages, 256 threads, 2 CTAs/SM (R5 proven)
#define SMEM2_BYTES (3 * STAGE_BYTES)      // 110592

// ---------------- device scratch ----------------
__device__ __align__(256) __half g_W1T[(size_t)HID * DIN];
__device__ __align__(256) __half g_W2T[(size_t)HID * HID];
__device__ __align__(256) __half g_H1 [(size_t)NROWS * HID];
__device__ __align__(256) float  g_H2 [(size_t)NROWS * HID];

// ---------------- PTX helpers ----------------
__device__ __forceinline__ uint32_t smem_u32(const void* p) {
    uint32_t a;
    asm("{ .reg .u64 t; cvta.to.shared.u64 t, %1; cvt.u32.u64 %0, t; }" : "=r"(a) : "l"(p));
    return a;
}

#define CP_ASYNC16(dst, src) \
    asm volatile("cp.async.cg.shared.global [%0], [%1], 16;" :: "r"(dst), "l"(src) : "memory")
#define CP_ASYNC_COMMIT() asm volatile("cp.async.commit_group;" ::: "memory")
#define CP_ASYNC_WAIT0()  asm volatile("cp.async.wait_group 0;" ::: "memory")
#define CP_ASYNC_WAIT1()  asm volatile("cp.async.wait_group 1;" ::: "memory")

__device__ __forceinline__ void ldm_x4(uint32_t& r0, uint32_t& r1, uint32_t& r2, uint32_t& r3,
                                       uint32_t addr) {
    asm volatile("ldmatrix.sync.aligned.m8n8.x4.shared.b16 {%0,%1,%2,%3}, [%4];"
                 : "=r"(r0), "=r"(r1), "=r"(r2), "=r"(r3) : "r"(addr));
}

__device__ __forceinline__ void sts64(uint32_t addr, uint32_t lo, uint32_t hi) {
    asm volatile("st.shared.v2.u32 [%0], {%1,%2};" :: "r"(addr), "r"(lo), "r"(hi) : "memory");
}

__device__ __forceinline__ uint32_t packh2(float lo, float hi) {
    __half2 h = __floats2half2_rn(lo, hi);
    return *reinterpret_cast<uint32_t*>(&h);
}

__device__ __forceinline__ void mma16816(float* d, const uint32_t* a, const uint32_t* b) {
    asm volatile(
        "mma.sync.aligned.m16n8k16.row.col.f32.f16.f16.f32 "
        "{%0,%1,%2,%3}, {%4,%5,%6,%7}, {%8,%9}, {%0,%1,%2,%3};"
        : "+f"(d[0]), "+f"(d[1]), "+f"(d[2]), "+f"(d[3])
        : "r"(a[0]), "r"(a[1]), "r"(a[2]), "r"(a[3]), "r"(b[0]), "r"(b[1]));
}

// ---------------- weight transpose (f32 -> f16, [R,C] -> [C,R]) ----------------
__global__ void __launch_bounds__(256) transpose_f32_to_f16(const float* __restrict__ in,
                                                            __half* __restrict__ out,
                                                            int R, int C) {
    __shared__ float tile[32][33];
    int c0 = blockIdx.x * 32, r0 = blockIdx.y * 32;
    int x = threadIdx.x, y = threadIdx.y;  // block (32, 8)
    #pragma unroll
    for (int j = 0; j < 32; j += 8)
        tile[y + j][x] = in[(size_t)(r0 + y + j) * C + (c0 + x)];
    __syncthreads();
    #pragma unroll
    for (int j = 0; j < 32; j += 8)
        out[(size_t)(c0 + y + j) * R + (r0 + x)] = __float2half_rn(tile[x][y + j]);
}

// ---------------- GEMM1: warp-specialized fused fp32->fp16 convert ----------------
// H1[M, N] = X[M, K] (fp32) @ W1T[N, K]^T (f16) + b1, out f16.
// Warps 0-7: R5 compute loop (ldmatrix fp16 + HMMA).  Warps 8-11: producers
// (LDG.128 fp32 X -> F2FP pack -> STS.64 fp16; cp.async for B). 2-stage ping-pong.
__global__ void __launch_bounds__(384, 1)
gemm1_kernel(const float* __restrict__ A, const __half* __restrict__ B,
             const float* __restrict__ bias, __half* __restrict__ Cout,
             int K, int nk) {
    extern __shared__ char smem[];
    const uint32_t sb = smem_u32(smem);
    const int tid  = threadIdx.x;
    const int wid  = tid >> 5, lane = tid & 31;
    const int m0   = blockIdx.y * BM;
    const int n0   = blockIdx.x * BN;

    if (wid >= 8) {
        // ================= producer warps (4 warps = 128 threads) =================
        const int ptid = tid - 256;            // 0..127
        const int ac   = ptid & 15;            // fp32 16B chunk within 256B row (0..15)
        const int ar   = ptid >> 4;            // 0..7 (rows ar + 8p)
        const int bc2  = ptid & 7;             // f16 16B chunk within 128B row (0..7)
        const int brw  = ptid >> 3;            // 0..15 (rows brw + 16h)

        const float4* gA = reinterpret_cast<const float4*>(A + (size_t)(m0 + ar) * K) + ac;
        const size_t aK4 = (size_t)K / 4;      // float4 per row
        const char*  gB  = reinterpret_cast<const char*>(B) + ((size_t)(n0 + brw) * K) * 2 + bc2 * 16;
        const size_t bRS = (size_t)16 * K * 2; // +16 rows in bytes

        auto fill_stage = [&](int kc, int s) {
            const uint32_t abase = sb + s * STAGE_BYTES;
            const uint32_t bbase = abase + BM * ROWB;
            // B: fire-and-forget cp.async (16KB)
            const char* srcB = gB + (size_t)kc * (BK * 2);
            #pragma unroll
            for (int h = 0; h < 8; h++)
                CP_ASYNC16(bbase + (brw + 16 * h) * ROWB + bc2 * 16, srcB + h * bRS);
            CP_ASYNC_COMMIT();
            // A: 16 coalesced LDG.128 (fp32), convert, STS.64
            const float4* srcA = gA + (size_t)kc * (BK / 4);
            float4 v[16];
            #pragma unroll
            for (int p = 0; p < 16; p++)
                v[p] = srcA[(size_t)8 * p * aK4];
            #pragma unroll
            for (int p = 0; p < 16; p++) {
                uint32_t lo = packh2(v[p].x, v[p].y);
                uint32_t hi = packh2(v[p].z, v[p].w);
                sts64(abase + (ar + 8 * p) * ROWB + ac * 8, lo, hi);
            }
            CP_ASYNC_WAIT0();
        };

        fill_stage(0, 0);
        __syncthreads();
        for (int kc = 0; kc < nk; kc++) {
            if (kc + 1 < nk) fill_stage(kc + 1, (kc + 1) & 1);
            __syncthreads();
        }
        return;
    }

    // ================= compute warps (8 warps, R5 mainloop) =================
    const int wm = wid & 1;           // 0..1 -> M offset (x64)
    const int wn = wid >> 1;          // 0..3 -> N offset (x32)

    const int a_row = lane & 15, a_k8 = lane >> 4;                             // A m16k16 .x4
    const int b_row = (lane & 7) + ((lane >> 4) << 3), b_k8 = (lane >> 3) & 1; // B 2x n8k16 .x4

    float acc[4][4][4];
    #pragma unroll
    for (int i = 0; i < 4; i++)
        #pragma unroll
        for (int j = 0; j < 4; j++)
            #pragma unroll
            for (int r = 0; r < 4; r++) acc[i][j][r] = 0.f;

    __syncthreads();   // matches producer's post-prologue barrier
    for (int kc = 0; kc < nk; kc++) {
        const uint32_t abase = sb + (kc & 1) * STAGE_BYTES;
        const uint32_t bbase = abase + BM * ROWB;

        #pragma unroll
        for (int kk = 0; kk < 4; kk++) {   // four k16 steps per BK=64
            uint32_t af[4][4], bf[4][2];
            #pragma unroll
            for (int mi = 0; mi < 4; mi++) {
                uint32_t addr = abase + (wm * 64 + mi * 16 + a_row) * ROWB + (kk * 2 + a_k8) * 16;
                ldm_x4(af[mi][0], af[mi][1], af[mi][2], af[mi][3], addr);
            }
            #pragma unroll
            for (int nb = 0; nb < 2; nb++) {
                uint32_t addr = bbase + (wn * 32 + nb * 16 + b_row) * ROWB + (kk * 2 + b_k8) * 16;
                uint32_t r0, r1, r2, r3;
                ldm_x4(r0, r1, r2, r3, addr);
                bf[nb * 2][0] = r0;     bf[nb * 2][1] = r1;
                bf[nb * 2 + 1][0] = r2; bf[nb * 2 + 1][1] = r3;
            }
            #pragma unroll
            for (int mi = 0; mi < 4; mi++)
                #pragma unroll
                for (int nj = 0; nj < 4; nj++)
                    mma16816(acc[mi][nj], af[mi], bf[nj]);
        }
        __syncthreads();
    }

    // epilogue: +bias, f16 out
    const int tq = lane >> 2, tr = lane & 3;
    #pragma unroll
    for (int nj = 0; nj < 4; nj++) {
        const int col = n0 + wn * 32 + nj * 8 + tr * 2;
        const float bx = bias[col], by = bias[col + 1];
        #pragma unroll
        for (int mi = 0; mi < 4; mi++) {
            const int row = m0 + wm * 64 + mi * 16 + tq;
            __half2 h0 = __floats2half2_rn(acc[mi][nj][0] + bx, acc[mi][nj][1] + by);
            __half2 h1 = __floats2half2_rn(acc[mi][nj][2] + bx, acc[mi][nj][3] + by);
            *reinterpret_cast<__half2*>(Cout + (size_t)row * HID + col) = h0;
            *reinterpret_cast<__half2*>(Cout + (size_t)(row + 8) * HID + col) = h1;
        }
    }
}

// ---------------- GEMM2: f16 A/B, BK=64, 3-stage cp.async, relu(+bias), f32 out ----------------
__global__ void __launch_bounds__(256, 2)
gemm2_kernel(const __half* __restrict__ A, const __half* __restrict__ B,
             const float* __restrict__ bias, float* __restrict__ Cout,
             int K, int nk) {
    extern __shared__ char smem[];
    const uint32_t sb = smem_u32(smem);
    const int tid  = threadIdx.x;
    const int wid  = tid >> 5, lane = tid & 31;
    const int wm   = wid & 1;
    const int wn   = wid >> 1;
    const int m0   = blockIdx.y * BM;
    const int n0   = blockIdx.x * BN;

    const int cr = tid >> 3;
    const int cc = (tid & 7) * 16;

    const char* gA = reinterpret_cast<const char*>(A) + ((size_t)(m0 + cr) * K) * 2 + cc;
    const char* gB = reinterpret_cast<const char*>(B) + ((size_t)(n0 + cr) * K) * 2 + cc;
    const size_t rstride = (size_t)32 * K * 2;

    auto issue_stage = [&](int kc, int s) {
        const uint32_t abase = sb + s * STAGE_BYTES;
        const uint32_t bbase = abase + BM * ROWB;
        const size_t koff = (size_t)kc * (BK * 2);
        #pragma unroll
        for (int h = 0; h < 4; h++)
            CP_ASYNC16(abase + (cr + h * 32) * ROWB + cc, gA + koff + h * rstride);
        #pragma unroll
        for (int h = 0; h < 4; h++)
            CP_ASYNC16(bbase + (cr + h * 32) * ROWB + cc, gB + koff + h * rstride);
    };

    const int a_row = lane & 15, a_k8 = lane >> 4;
    const int b_row = (lane & 7) + ((lane >> 4) << 3), b_k8 = (lane >> 3) & 1;

    float acc[4][4][4];
    #pragma unroll
    for (int i = 0; i < 4; i++)
        #pragma unroll
        for (int j = 0; j < 4; j++)
            #pragma unroll
            for (int r = 0; r < 4; r++) acc[i][j][r] = 0.f;

    issue_stage(0, 0); CP_ASYNC_COMMIT();
    if (nk > 1) issue_stage(1, 1); CP_ASYNC_COMMIT();

    int s = 0, s2 = 2;
    for (int kc = 0; kc < nk; kc++) {
        CP_ASYNC_WAIT1();
        __syncthreads();

        if (kc + 2 < nk) issue_stage(kc + 2, s2);
        CP_ASYNC_COMMIT();

        const uint32_t abase = sb + s * STAGE_BYTES;
        const uint32_t bbase = abase + BM * ROWB;

        #pragma unroll
        for (int kk = 0; kk < 4; kk++) {
            uint32_t af[4][4], bf[4][2];
            #pragma unroll
            for (int mi = 0; mi < 4; mi++) {
                uint32_t addr = abase + (wm * 64 + mi * 16 + a_row) * ROWB + (kk * 2 + a_k8) * 16;
                ldm_x4(af[mi][0], af[mi][1], af[mi][2], af[mi][3], addr);
            }
            #pragma unroll
            for (int nb = 0; nb < 2; nb++) {
                uint32_t addr = bbase + (wn * 32 + nb * 16 + b_row) * ROWB + (kk * 2 + b_k8) * 16;
                uint32_t r0, r1, r2, r3;
                ldm_x4(r0, r1, r2, r3, addr);
                bf[nb * 2][0] = r0;     bf[nb * 2][1] = r1;
                bf[nb * 2 + 1][0] = r2; bf[nb * 2 + 1][1] = r3;
            }
            #pragma unroll
            for (int mi = 0; mi < 4; mi++)
                #pragma unroll
                for (int nj = 0; nj < 4; nj++)
                    mma16816(acc[mi][nj], af[mi], bf[nj]);
        }
        s = (s == 2) ? 0 : s + 1;
        s2 = (s2 == 2) ? 0 : s2 + 1;
    }

    const int tq = lane >> 2, tr = lane & 3;
    #pragma unroll
    for (int nj = 0; nj < 4; nj++) {
        const int col = n0 + wn * 32 + nj * 8 + tr * 2;
        const float bx = bias[col], by = bias[col + 1];
        #pragma unroll
        for (int mi = 0; mi < 4; mi++) {
            const int row = m0 + wm * 64 + mi * 16 + tq;
            float2 f0 = make_float2(fmaxf(acc[mi][nj][0] + bx, 0.f), fmaxf(acc[mi][nj][1] + by, 0.f));
            float2 f1 = make_float2(fmaxf(acc[mi][nj][2] + bx, 0.f), fmaxf(acc[mi][nj][3] + by, 0.f));
            *reinterpret_cast<float2*>(Cout + (size_t)row * HID + col) = f0;
            *reinterpret_cast<float2*>(Cout + (size_t)(row + 8) * HID + col) = f1;
        }
    }
}

// ---------------- heads: logits softmax + box regression ----------------
__global__ void __launch_bounds__(128) heads_kernel(const float* __restrict__ H,
                                                    const float* __restrict__ Wc, const float* __restrict__ bc,
                                                    const float* __restrict__ Wr, const float* __restrict__ br,
                                                    float* __restrict__ out) {
    const int row = blockIdx.x;
    const int tid = threadIdx.x, lane = tid & 31, w = tid >> 5;
    __shared__ float part[4 * 16];
    __shared__ float res[16];

    float acc[16];
    #pragma unroll
    for (int o = 0; o < 16; o++) acc[o] = 0.f;

    const float* h = H + (size_t)row * HID;
    const float4* Wc4 = reinterpret_cast<const float4*>(Wc);
    const float4* Wr4 = reinterpret_cast<const float4*>(Wr);
    for (int k = tid; k < HID; k += 128) {
        float hv = h[k];
        float4 c = Wc4[k];
        acc[0] += hv * c.x; acc[1] += hv * c.y; acc[2] += hv * c.z; acc[3] += hv * c.w;
        float4 r0 = Wr4[k * 3], r1 = Wr4[k * 3 + 1], r2 = Wr4[k * 3 + 2];
        acc[4]  += hv * r0.x; acc[5]  += hv * r0.y; acc[6]  += hv * r0.z; acc[7]  += hv * r0.w;
        acc[8]  += hv * r1.x; acc[9]  += hv * r1.y; acc[10] += hv * r1.z; acc[11] += hv * r1.w;
        acc[12] += hv * r2.x; acc[13] += hv * r2.y; acc[14] += hv * r2.z; acc[15] += hv * r2.w;
    }
    #pragma unroll
    for (int o = 0; o < 16; o++) {
        float v = acc[o];
        v += __shfl_xor_sync(0xffffffffu, v, 16);
        v += __shfl_xor_sync(0xffffffffu, v, 8);
        v += __shfl_xor_sync(0xffffffffu, v, 4);
        v += __shfl_xor_sync(0xffffffffu, v, 2);
        v += __shfl_xor_sync(0xffffffffu, v, 1);
        if (lane == 0) part[w * 16 + o] = v;
    }
    __syncthreads();
    if (tid < 16) {
        float v = part[tid] + part[16 + tid] + part[32 + tid] + part[48 + tid];
        v += (tid < 4) ? bc[tid] : br[tid - 4];
        res[tid] = v;
    }
    __syncthreads();
    if (tid == 0) {
        float m = fmaxf(fmaxf(res[0], res[1]), fmaxf(res[2], res[3]));
        float e0 = expf(res[0] - m), e1 = expf(res[1] - m), e2 = expf(res[2] - m), e3 = expf(res[3] - m);
        float inv = 1.f / (e0 + e1 + e2 + e3);
        out[(size_t)row * 4 + 0] = e0 * inv;
        out[(size_t)row * 4 + 1] = e1 * inv;
        out[(size_t)row * 4 + 2] = e2 * inv;
        out[(size_t)row * 4 + 3] = e3 * inv;
    }
    if (tid >= 4 && tid < 16)
        out[(size_t)NROWS * 4 + (size_t)row * 12 + (tid - 4)] = res[tid];
}

// ---------------- launch ----------------
extern "C" void kernel_launch(void* const* d_in, const int* in_sizes, int n_in,
                              void* d_out, int out_size) {
    (void)in_sizes; (void)n_in; (void)out_size;
    const float* X  = (const float*)d_in[0];
    const float* W1 = (const float*)d_in[1];
    const float* b1 = (const float*)d_in[2];
    const float* W2 = (const float*)d_in[3];
    const float* b2 = (const float*)d_in[4];
    const float* Wc = (const float*)d_in[5];
    const float* bc = (const float*)d_in[6];
    const float* Wr = (const float*)d_in[7];
    const float* br = (const float*)d_in[8];
    float* out = (float*)d_out;

    void *pW1T, *pW2T, *pH1, *pH2;
    cudaGetSymbolAddress(&pW1T, g_W1T);
    cudaGetSymbolAddress(&pW2T, g_W2T);
    cudaGetSymbolAddress(&pH1,  g_H1);
    cudaGetSymbolAddress(&pH2,  g_H2);

    cudaFuncSetAttribute(gemm1_kernel, cudaFuncAttributeMaxDynamicSharedMemorySize, SMEM1_BYTES);
    cudaFuncSetAttribute(gemm2_kernel, cudaFuncAttributeMaxDynamicSharedMemorySize, SMEM2_BYTES);

    // 1) W1 [DIN, HID] -> W1T [HID, DIN] f16 ; W2 -> W2T f16
    transpose_f32_to_f16<<<dim3(HID / 32, DIN / 32), dim3(32, 8)>>>(W1, (__half*)pW1T, DIN, HID);
    transpose_f32_to_f16<<<dim3(HID / 32, HID / 32), dim3(32, 8)>>>(W2, (__half*)pW2T, HID, HID);
    // 2) H1 = X @ W1 + b1  (fp32 X converted by producer warps, f16 out)
    gemm1_kernel<<<dim3(HID / BN, NROWS / BM), 384, SMEM1_BYTES>>>(
        X, (const __half*)pW1T, b1, (__half*)pH1, DIN, DIN / BK);
    // 3) H2 = relu(H1 @ W2 + b2)  (f32 out)
    gemm2_kernel<<<dim3(HID / BN, NROWS / BM), 256, SMEM2_BYTES>>>(
        (const __half*)pH1, (const __half*)pW2T, b2, (float*)pH2, HID, HID / BK);
    // 4) heads
    heads_kernel<<<NROWS, 128>>>((const float*)pH2, Wc, bc, Wr, br, out);
}

// round 8
// speedup vs baseline: 1.3185x; 1.3156x over previous
#include <cuda_runtime.h>
#include <cuda_fp16.h>
#include <cstdint>

// ---------------- problem constants ----------------
#define NROWS 8192
#define DIN   12544
#define HID   1024

// ---------------- GEMM tile config: 128x128 tile, 4 warps (64x64 warp tile) ----------------
#define BM 128
#define BN 128
#define BK 64
#define ROWB 144                           // 128B data + 16B pad (conflict-free ldmatrix)
#define STAGE_BYTES ((BM + BN) * ROWB)     // 36864
#define SMEM_BYTES (3 * STAGE_BYTES)       // 110592 -> 2 CTAs/SM (221KB of 228KB)

// ---------------- device scratch ----------------
__device__ __align__(256) __half g_Xh [(size_t)NROWS * DIN];
__device__ __align__(256) __half g_W1T[(size_t)HID * DIN];
__device__ __align__(256) __half g_W2T[(size_t)HID * HID];
__device__ __align__(256) __half g_H1 [(size_t)NROWS * HID];
__device__ __align__(256) float  g_H2 [(size_t)NROWS * HID];

// ---------------- PTX helpers ----------------
__device__ __forceinline__ uint32_t smem_u32(const void* p) {
    uint32_t a;
    asm("{ .reg .u64 t; cvta.to.shared.u64 t, %1; cvt.u32.u64 %0, t; }" : "=r"(a) : "l"(p));
    return a;
}

#define CP_ASYNC16(dst, src) \
    asm volatile("cp.async.cg.shared.global [%0], [%1], 16;" :: "r"(dst), "l"(src) : "memory")
#define CP_ASYNC_COMMIT() asm volatile("cp.async.commit_group;" ::: "memory")
#define CP_ASYNC_WAIT1()  asm volatile("cp.async.wait_group 1;" ::: "memory")

__device__ __forceinline__ void ldm_x4(uint32_t& r0, uint32_t& r1, uint32_t& r2, uint32_t& r3,
                                       uint32_t addr) {
    asm volatile("ldmatrix.sync.aligned.m8n8.x4.shared.b16 {%0,%1,%2,%3}, [%4];"
                 : "=r"(r0), "=r"(r1), "=r"(r2), "=r"(r3) : "r"(addr));
}

__device__ __forceinline__ void mma16816(float* d, const uint32_t* a, const uint32_t* b) {
    asm volatile(
        "mma.sync.aligned.m16n8k16.row.col.f32.f16.f16.f32 "
        "{%0,%1,%2,%3}, {%4,%5,%6,%7}, {%8,%9}, {%0,%1,%2,%3};"
        : "+f"(d[0]), "+f"(d[1]), "+f"(d[2]), "+f"(d[3])
        : "r"(a[0]), "r"(a[1]), "r"(a[2]), "r"(a[3]), "r"(b[0]), "r"(b[1]));
}

// ---------------- conversion kernels ----------------
__global__ void __launch_bounds__(256) f32_to_f16_kernel(const float* __restrict__ in,
                                                         __half* __restrict__ out, size_t n8) {
    size_t i = (size_t)blockIdx.x * blockDim.x + threadIdx.x;
    if (i >= n8) return;
    const float4* p = reinterpret_cast<const float4*>(in) + i * 2;
    float4 a = p[0], b = p[1];
    __half2 h0 = __floats2half2_rn(a.x, a.y), h1 = __floats2half2_rn(a.z, a.w);
    __half2 h2 = __floats2half2_rn(b.x, b.y), h3 = __floats2half2_rn(b.z, b.w);
    uint4 v;
    v.x = *reinterpret_cast<uint32_t*>(&h0);
    v.y = *reinterpret_cast<uint32_t*>(&h1);
    v.z = *reinterpret_cast<uint32_t*>(&h2);
    v.w = *reinterpret_cast<uint32_t*>(&h3);
    reinterpret_cast<uint4*>(out)[i] = v;
}

// in: [R, C] f32 row-major  ->  out: [C, R] f16 row-major (transpose + convert)
__global__ void __launch_bounds__(256) transpose_f32_to_f16(const float* __restrict__ in,
                                                            __half* __restrict__ out,
                                                            int R, int C) {
    __shared__ float tile[32][33];
    int c0 = blockIdx.x * 32, r0 = blockIdx.y * 32;
    int x = threadIdx.x, y = threadIdx.y;  // block (32, 8)
    #pragma unroll
    for (int j = 0; j < 32; j += 8)
        tile[y + j][x] = in[(size_t)(r0 + y + j) * C + (c0 + x)];
    __syncthreads();
    #pragma unroll
    for (int j = 0; j < 32; j += 8)
        out[(size_t)(c0 + y + j) * R + (r0 + x)] = __float2half_rn(tile[x][y + j]);
}

// ---------------- mma.sync GEMM: 128 threads / 4 warps, warp tile 64x64, 2 CTAs/SM ----------------
// C[M, N] = A[M, K] (f16, K-major) @ B[N, K]^T (f16, K-major) + bias
// MODE 0: out = half, +bias           (GEMM1 -> H1)
// MODE 1: out = float, relu(+bias)    (GEMM2 -> H2)
template<int MODE>
__global__ void __launch_bounds__(128, 2)
gemm_f16_kernel(const __half* __restrict__ A, const __half* __restrict__ B,
                const float* __restrict__ bias, void* __restrict__ Cout,
                int K, int nk) {
    extern __shared__ char smem[];
    const uint32_t sb = smem_u32(smem);
    const int tid  = threadIdx.x;
    const int wid  = tid >> 5, lane = tid & 31;
    const int wm   = wid & 1;            // 0..1 -> M offset (x64)
    const int wn   = wid >> 1;           // 0..1 -> N offset (x64)
    const int m0   = blockIdx.y * BM;
    const int n0   = blockIdx.x * BN;

    // global->smem mapping: 16B chunks, 8 per 128B row-slice; 128 threads cover 16 rows/pass
    const int cr = tid >> 3;             // 0..15
    const int cc = (tid & 7) * 16;       // byte offset within 128B K-slice

    const char* gA = reinterpret_cast<const char*>(A) + ((size_t)(m0 + cr) * K) * 2 + cc;
    const char* gB = reinterpret_cast<const char*>(B) + ((size_t)(n0 + cr) * K) * 2 + cc;
    const size_t rstride = (size_t)16 * K * 2;   // +16 rows

    auto issue_stage = [&](int kc, int s) {
        const uint32_t abase = sb + s * STAGE_BYTES;
        const uint32_t bbase = abase + BM * ROWB;
        const size_t koff = (size_t)kc * (BK * 2);
        #pragma unroll
        for (int h = 0; h < 8; h++)  // A: 128 rows
            CP_ASYNC16(abase + (cr + h * 16) * ROWB + cc, gA + koff + h * rstride);
        #pragma unroll
        for (int h = 0; h < 8; h++)  // B: 128 rows
            CP_ASYNC16(bbase + (cr + h * 16) * ROWB + cc, gB + koff + h * rstride);
    };

    // ldmatrix per-lane offsets
    const int a_row = lane & 15, a_k8 = lane >> 4;                             // A m16k16 .x4
    const int b_row = (lane & 7) + ((lane >> 4) << 3), b_k8 = (lane >> 3) & 1; // B 2x n8k16 .x4

    float acc[4][8][4];
    #pragma unroll
    for (int i = 0; i < 4; i++)
        #pragma unroll
        for (int j = 0; j < 8; j++)
            #pragma unroll
            for (int r = 0; r < 4; r++) acc[i][j][r] = 0.f;

    // prologue: issue 2 stages
    issue_stage(0, 0); CP_ASYNC_COMMIT();
    if (nk > 1) issue_stage(1, 1); CP_ASYNC_COMMIT();

    int s = 0, s2 = 2;  // s = compute stage, s2 = stage to fill
    for (int kc = 0; kc < nk; kc++) {
        CP_ASYNC_WAIT1();
        __syncthreads();   // stage s ready; all warps done with buffer s2 (computed iter kc-1)

        if (kc + 2 < nk) issue_stage(kc + 2, s2);
        CP_ASYNC_COMMIT();

        const uint32_t abase = sb + s * STAGE_BYTES;
        const uint32_t bbase = abase + BM * ROWB;

        #pragma unroll
        for (int kk = 0; kk < 4; kk++) {   // four k16 steps per BK=64
            uint32_t af[4][4], bf[8][2];
            #pragma unroll
            for (int mi = 0; mi < 4; mi++) {
                uint32_t addr = abase + (wm * 64 + mi * 16 + a_row) * ROWB + (kk * 2 + a_k8) * 16;
                ldm_x4(af[mi][0], af[mi][1], af[mi][2], af[mi][3], addr);
            }
            #pragma unroll
            for (int nb = 0; nb < 4; nb++) {
                uint32_t addr = bbase + (wn * 64 + nb * 16 + b_row) * ROWB + (kk * 2 + b_k8) * 16;
                uint32_t r0, r1, r2, r3;
                ldm_x4(r0, r1, r2, r3, addr);
                bf[nb * 2][0] = r0;     bf[nb * 2][1] = r1;
                bf[nb * 2 + 1][0] = r2; bf[nb * 2 + 1][1] = r3;
            }
            #pragma unroll
            for (int mi = 0; mi < 4; mi++)
                #pragma unroll
                for (int nj = 0; nj < 8; nj++)
                    mma16816(acc[mi][nj], af[mi], bf[nj]);
        }
        s = (s == 2) ? 0 : s + 1;
        s2 = (s2 == 2) ? 0 : s2 + 1;
    }

    // ---------------- epilogue ----------------
    const int tq = lane >> 2;          // row within 16 (0..7)
    const int tr = lane & 3;           // col pair (0..3)
    #pragma unroll
    for (int nj = 0; nj < 8; nj++) {
        const int col = n0 + wn * 64 + nj * 8 + tr * 2;
        const float bx = bias[col], by = bias[col + 1];
        #pragma unroll
        for (int mi = 0; mi < 4; mi++) {
            const int row = m0 + wm * 64 + mi * 16 + tq;
            if (MODE == 0) {
                __half* C = reinterpret_cast<__half*>(Cout);
                __half2 h0 = __floats2half2_rn(acc[mi][nj][0] + bx, acc[mi][nj][1] + by);
                __half2 h1 = __floats2half2_rn(acc[mi][nj][2] + bx, acc[mi][nj][3] + by);
                *reinterpret_cast<__half2*>(C + (size_t)row * HID + col) = h0;
                *reinterpret_cast<__half2*>(C + (size_t)(row + 8) * HID + col) = h1;
            } else {
                float* C = reinterpret_cast<float*>(Cout);
                float2 f0 = make_float2(fmaxf(acc[mi][nj][0] + bx, 0.f), fmaxf(acc[mi][nj][1] + by, 0.f));
                float2 f1 = make_float2(fmaxf(acc[mi][nj][2] + bx, 0.f), fmaxf(acc[mi][nj][3] + by, 0.f));
                *reinterpret_cast<float2*>(C + (size_t)row * HID + col) = f0;
                *reinterpret_cast<float2*>(C + (size_t)(row + 8) * HID + col) = f1;
            }
        }
    }
}

// ---------------- heads: logits softmax + box regression ----------------
__global__ void __launch_bounds__(128) heads_kernel(const float* __restrict__ H,
                                                    const float* __restrict__ Wc, const float* __restrict__ bc,
                                                    const float* __restrict__ Wr, const float* __restrict__ br,
                                                    float* __restrict__ out) {
    const int row = blockIdx.x;
    const int tid = threadIdx.x, lane = tid & 31, w = tid >> 5;
    __shared__ float part[4 * 16];
    __shared__ float res[16];

    float acc[16];
    #pragma unroll
    for (int o = 0; o < 16; o++) acc[o] = 0.f;

    const float* h = H + (size_t)row * HID;
    const float4* Wc4 = reinterpret_cast<const float4*>(Wc);
    const float4* Wr4 = reinterpret_cast<const float4*>(Wr);
    for (int k = tid; k < HID; k += 128) {
        float hv = h[k];
        float4 c = Wc4[k];
        acc[0] += hv * c.x; acc[1] += hv * c.y; acc[2] += hv * c.z; acc[3] += hv * c.w;
        float4 r0 = Wr4[k * 3], r1 = Wr4[k * 3 + 1], r2 = Wr4[k * 3 + 2];
        acc[4]  += hv * r0.x; acc[5]  += hv * r0.y; acc[6]  += hv * r0.z; acc[7]  += hv * r0.w;
        acc[8]  += hv * r1.x; acc[9]  += hv * r1.y; acc[10] += hv * r1.z; acc[11] += hv * r1.w;
        acc[12] += hv * r2.x; acc[13] += hv * r2.y; acc[14] += hv * r2.z; acc[15] += hv * r2.w;
    }
    #pragma unroll
    for (int o = 0; o < 16; o++) {
        float v = acc[o];
        v += __shfl_xor_sync(0xffffffffu, v, 16);
        v += __shfl_xor_sync(0xffffffffu, v, 8);
        v += __shfl_xor_sync(0xffffffffu, v, 4);
        v += __shfl_xor_sync(0xffffffffu, v, 2);
        v += __shfl_xor_sync(0xffffffffu, v, 1);
        if (lane == 0) part[w * 16 + o] = v;
    }
    __syncthreads();
    if (tid < 16) {
        float v = part[tid] + part[16 + tid] + part[32 + tid] + part[48 + tid];
        v += (tid < 4) ? bc[tid] : br[tid - 4];
        res[tid] = v;
    }
    __syncthreads();
    if (tid == 0) {
        float m = fmaxf(fmaxf(res[0], res[1]), fmaxf(res[2], res[3]));
        float e0 = expf(res[0] - m), e1 = expf(res[1] - m), e2 = expf(res[2] - m), e3 = expf(res[3] - m);
        float inv = 1.f / (e0 + e1 + e2 + e3);
        out[(size_t)row * 4 + 0] = e0 * inv;
        out[(size_t)row * 4 + 1] = e1 * inv;
        out[(size_t)row * 4 + 2] = e2 * inv;
        out[(size_t)row * 4 + 3] = e3 * inv;
    }
    if (tid >= 4 && tid < 16)
        out[(size_t)NROWS * 4 + (size_t)row * 12 + (tid - 4)] = res[tid];
}

// ---------------- launch ----------------
extern "C" void kernel_launch(void* const* d_in, const int* in_sizes, int n_in,
                              void* d_out, int out_size) {
    (void)in_sizes; (void)n_in; (void)out_size;
    const float* X  = (const float*)d_in[0];
    const float* W1 = (const float*)d_in[1];
    const float* b1 = (const float*)d_in[2];
    const float* W2 = (const float*)d_in[3];
    const float* b2 = (const float*)d_in[4];
    const float* Wc = (const float*)d_in[5];
    const float* bc = (const float*)d_in[6];
    const float* Wr = (const float*)d_in[7];
    const float* br = (const float*)d_in[8];
    float* out = (float*)d_out;

    void *pXh, *pW1T, *pW2T, *pH1, *pH2;
    cudaGetSymbolAddress(&pXh,  g_Xh);
    cudaGetSymbolAddress(&pW1T, g_W1T);
    cudaGetSymbolAddress(&pW2T, g_W2T);
    cudaGetSymbolAddress(&pH1,  g_H1);
    cudaGetSymbolAddress(&pH2,  g_H2);

    cudaFuncSetAttribute(gemm_f16_kernel<0>, cudaFuncAttributeMaxDynamicSharedMemorySize, SMEM_BYTES);
    cudaFuncSetAttribute(gemm_f16_kernel<1>, cudaFuncAttributeMaxDynamicSharedMemorySize, SMEM_BYTES);

    // 1) X -> fp16
    {
        size_t n8 = (size_t)NROWS * DIN / 8;
        f32_to_f16_kernel<<<(unsigned)((n8 + 255) / 256), 256>>>(X, (__half*)pXh, n8);
    }
    // 2) W1 [DIN, HID] -> W1T [HID, DIN] f16 ; W2 -> W2T f16
    transpose_f32_to_f16<<<dim3(HID / 32, DIN / 32), dim3(32, 8)>>>(W1, (__half*)pW1T, DIN, HID);
    transpose_f32_to_f16<<<dim3(HID / 32, HID / 32), dim3(32, 8)>>>(W2, (__half*)pW2T, HID, HID);
    // 3) H1 = X @ W1 + b1          (f16 out)
    gemm_f16_kernel<0><<<dim3(HID / BN, NROWS / BM), 128, SMEM_BYTES>>>(
        (const __half*)pXh, (const __half*)pW1T, b1, pH1, DIN, DIN / BK);
    // 4) H2 = relu(H1 @ W2 + b2)   (f32 out)
    gemm_f16_kernel<1><<<dim3(HID / BN, NROWS / BM), 128, SMEM_BYTES>>>(
        (const __half*)pH1, (const __half*)pW2T, b2, pH2, HID, HID / BK);
    // 5) heads
    heads_kernel<<<NROWS, 128>>>((const float*)pH2, Wc, bc, Wr, br, out);
}